// round 12
// baseline (speedup 1.0000x reference)
#include <cuda_runtime.h>
#include <cuda_fp16.h>
#include <cstdint>

// Problem constants
#define BB 8
#define CC 512
#define OO 512
#define MTOT 4608          // 9 taps * 512 o
#define KK 512
#define KCG 64             // K per chunk
#define NKC 8              // KK / KCG
#define LDRW 144           // W smem row stride (128B data + 16B pad)
#define LDRX 272           // X smem row stride (256B data + 16B pad)
#define STG 35840          // per-stage: W 18432 + X 17408

// Scratch (no allocation allowed -> device globals)
__device__ float g_smod[BB * CC];                     // 1 + style @ fc_w^T + fc_b
__device__ float g_d[BB * OO];                        // demod scale
__device__ float g_w2t[CC * OO];                      // sum_k conv_w^2, [c][o]
__device__ __align__(16) __half g_w9[9 * OO * CC];    // [ji*512+o][c] fp16
__device__ __align__(16) __half g_xs[BB * CC * 1024]; // fp16(x*smod) [b][c][pix]
__device__ __align__(16) __half g_t[(size_t)BB * MTOT * 1024]; // taps [b][ji*512+o][pix]

// ---------------------------------------------------------------------------
__device__ __forceinline__ uint32_t smem_u32(const void* p) {
    uint32_t a;
    asm("{ .reg .u64 t; cvta.to.shared.u64 t, %1; cvt.u32.u64 %0, t; }"
        : "=r"(a) : "l"(p));
    return a;
}
#define CP_ASYNC16(dst, src) \
    asm volatile("cp.async.cg.shared.global [%0], [%1], 16;\n" \
                 :: "r"(dst), "l"(__cvta_generic_to_global(src)))
#define CP_COMMIT()  asm volatile("cp.async.commit_group;\n" ::: "memory")
#define CP_WAIT1()   asm volatile("cp.async.wait_group 1;\n" ::: "memory")
#define CP_WAIT0()   asm volatile("cp.async.wait_group 0;\n" ::: "memory")

#define LDMATRIX_X4(r, addr) \
    asm volatile("ldmatrix.sync.aligned.m8n8.x4.shared.b16 {%0,%1,%2,%3}, [%4];\n" \
                 : "=r"((r)[0]), "=r"((r)[1]), "=r"((r)[2]), "=r"((r)[3]) : "r"(addr))
#define LDMATRIX_X4_T(r, addr) \
    asm volatile("ldmatrix.sync.aligned.m8n8.x4.trans.shared.b16 {%0,%1,%2,%3}, [%4];\n" \
                 : "=r"((r)[0]), "=r"((r)[1]), "=r"((r)[2]), "=r"((r)[3]) : "r"(addr))

#define MMA16816(d, a, b0v, b1v) \
    asm volatile("mma.sync.aligned.m16n8k16.row.col.f32.f16.f16.f32 " \
                 "{%0,%1,%2,%3},{%4,%5,%6,%7},{%8,%9},{%0,%1,%2,%3};\n" \
                 : "+f"((d)[0]), "+f"((d)[1]), "+f"((d)[2]), "+f"((d)[3]) \
                 : "r"((a)[0]), "r"((a)[1]), "r"((a)[2]), "r"((a)[3]), \
                   "r"(b0v), "r"(b1v))

// ---------------------------------------------------------------------------
// s[b][c] = 1 + fc_b[c] + sum_k style[b][k] * fc_w[c][k]
__global__ void k_style(const float* __restrict__ style,
                        const float* __restrict__ fc_w,
                        const float* __restrict__ fc_b) {
    __shared__ float ss[512];
    int b = blockIdx.x;
    int c = threadIdx.x;
    ss[c] = style[b * 512 + c];
    __syncthreads();
    const float4* wrow = (const float4*)(fc_w + (size_t)c * 512);
    float acc = 0.f;
#pragma unroll 4
    for (int k = 0; k < 128; k++) {
        float4 w4 = wrow[k];
        acc += w4.x * ss[4 * k + 0] + w4.y * ss[4 * k + 1]
             + w4.z * ss[4 * k + 2] + w4.w * ss[4 * k + 3];
    }
    g_smod[b * 512 + c] = acc + fc_b[c] + 1.0f;
}

// ---------------------------------------------------------------------------
// W9 prep: g_w9[(ji*512+o)*512+c] = fp16(conv_w[o][c][j][i]); also W2^T.
// Thread map: c fastest -> w9 writes coalesced.
__global__ void k_w9(const float* __restrict__ conv_w) {
    int t = blockIdx.x * 256 + threadIdx.x;   // 262144 threads
    int c = t & 511;
    int o = t >> 9;
    const float* wp = conv_w + ((size_t)o * 512 + c) * 9;
    float s2 = 0.f;
#pragma unroll
    for (int q = 0; q < 9; q++) {
        float w = wp[q];
        s2 += w * w;
        g_w9[((size_t)q * 512 + o) * 512 + c] = __float2half_rn(w);
    }
    g_w2t[c * 512 + o] = s2;
}

// ---------------------------------------------------------------------------
// d[b][o] = rsqrt( sum_c smod[b][c]^2 * W2[o][c] + 1e-8 )
__global__ void k_demod() {
    __shared__ float s2[512];
    int b = blockIdx.y;
    int o = blockIdx.x * 256 + threadIdx.x;
    {
        float a = g_smod[b * 512 + threadIdx.x];
        float bv = g_smod[b * 512 + threadIdx.x + 256];
        s2[threadIdx.x] = a * a;
        s2[threadIdx.x + 256] = bv * bv;
    }
    __syncthreads();
    float acc = 1e-8f;
#pragma unroll 4
    for (int c = 0; c < 512; c++)
        acc += s2[c] * g_w2t[c * 512 + o];
    g_d[b * 512 + o] = rsqrtf(acc);
}

// ---------------------------------------------------------------------------
// xs[b][c][pix] = fp16( x[b][c][pix] * smod[b][c] ), float4-vectorized
__global__ void k_xsplit(const float* __restrict__ x) {
    int i = blockIdx.x * 256 + threadIdx.x;      // 1,048,576 threads
    int e0 = i * 4;
    int b = e0 >> 19;
    int c = (e0 >> 10) & 511;
    float s = g_smod[b * 512 + c];
    float4 v = *(const float4*)(x + e0);
    __half2 h0 = __floats2half2_rn(v.x * s, v.y * s);
    __half2 h1 = __floats2half2_rn(v.z * s, v.w * s);
    uint2 pk;
    pk.x = *(uint32_t*)&h0;
    pk.y = *(uint32_t*)&h1;
    *(uint2*)((char*)g_xs + (size_t)e0 * 2) = pk;
}

// ---------------------------------------------------------------------------
// Dense tap GEMM: per b: T[m][pix] = sum_c W9[m][c] * xs[b][c][pix]
// m = ji*512+o (4608 rows). CTA tile 128m x 128pix, K=512 in 8 chunks of 64,
// double-buffered pure cp.async for BOTH operands (no gather!).
// A frags: ldmatrix (rows=m), B frags: ldmatrix.trans (X stored [c][pix]).
// smem stage s at s*35840: W@0 (128 x LDRW), X@18432 (64 x LDRX).
// Epilogue: accum -> fp16 smem tile -> coalesced 256B-row stores to g_t.
#define SMEM_REQ (2 * STG)

__global__ void __launch_bounds__(256, 2) k_gemm9(void) {
    extern __shared__ __align__(16) char smem_raw[];
    char* abase = smem_raw;
    uint32_t base = smem_u32(smem_raw);

    const int tid = threadIdx.x;
    const int wid = tid >> 5;
    const int lane = tid & 31;

    const int nbase = blockIdx.x * 128;          // pixel base
    const int mbase = blockIdx.y * 128;          // (ji,o) row base
    const int b = blockIdx.z;

    const __half* gw = g_w9 + (size_t)mbase * 512;
    const __half* gx = g_xs + ((size_t)b << 19) + nbase;   // [c][pix], row 1024

    // loader constants
    const int wl_row = tid >> 3, wl_seg = tid & 7;   // W: 32 rows/pass? 256thr/8=32 rows -> x4 passes
    const int xl_row = tid >> 4, xl_seg = tid & 15;  // X: 16 rows/pass -> x4 passes

    // warp tile: 2x4 warp grid -> warp M=64, N=32
    const int moff = (wid & 1) * 64;
    const int noff = (wid >> 1) * 32;
    const uint32_t aoff = (uint32_t)((moff + (lane & 15)) * LDRW + (lane >> 4) * 16);
    const uint32_t boff = (uint32_t)(((lane & 7) + ((lane >> 3) & 1) * 8) * LDRX
                                     + (noff + (lane >> 4) * 8) * 2);

    float acc[16][4];
#pragma unroll
    for (int q = 0; q < 16; q++)
#pragma unroll
        for (int r = 0; r < 4; r++) acc[q][r] = 0.f;

    // stage chunk kc into buffer bf
    auto stage = [&](int kc, int bf) {
        uint32_t wdst = base + bf * STG;
#pragma unroll
        for (int s = 0; s < 4; s++) {
            int row = wl_row + 32 * s;
            CP_ASYNC16(wdst + row * LDRW + wl_seg * 16,
                       gw + (size_t)row * 512 + kc * 64 + wl_seg * 8);
        }
        uint32_t xdst = wdst + 18432;
#pragma unroll
        for (int s = 0; s < 4; s++) {
            int row = xl_row + 16 * s;
            CP_ASYNC16(xdst + row * LDRX + xl_seg * 16,
                       gx + ((size_t)(kc * 64 + row) << 10) + xl_seg * 8);
        }
    };

    stage(0, 0); CP_COMMIT();

    for (int kc = 0; kc < NKC; kc++) {
        int bf = kc & 1;
        if (kc + 1 < NKC) { stage(kc + 1, bf ^ 1); CP_COMMIT(); }
        if (kc + 1 < NKC) CP_WAIT1(); else CP_WAIT0();
        __syncthreads();

        uint32_t wS = base + bf * STG;
        uint32_t xS = wS + 18432;
#pragma unroll
        for (int ks = 0; ks < 4; ks++) {
            uint32_t a[4][4], bb[2][4];
#pragma unroll
            for (int mi = 0; mi < 4; mi++)
                LDMATRIX_X4(a[mi], wS + aoff + ks * 32 + mi * 16 * LDRW);
#pragma unroll
            for (int nf = 0; nf < 2; nf++)
                LDMATRIX_X4_T(bb[nf], xS + boff + ks * 16 * LDRX + nf * 32);
#pragma unroll
            for (int mi = 0; mi < 4; mi++)
#pragma unroll
                for (int ni = 0; ni < 4; ni++)
                    MMA16816(acc[mi * 4 + ni], a[mi],
                             bb[ni >> 1][(ni & 1) * 2], bb[ni >> 1][(ni & 1) * 2 + 1]);
        }
        __syncthreads();
    }

    // ---- epilogue: fp32 accums -> fp16 smem tile -> coalesced store ----
    {
        __half* Dh = (__half*)abase;          // [128][136]
        int g = lane >> 2, t4 = lane & 3;
#pragma unroll
        for (int mi = 0; mi < 4; mi++)
#pragma unroll
            for (int ni = 0; ni < 4; ni++) {
                int row0 = moff + mi * 16 + g;
                int col = noff + ni * 8 + t4 * 2;
                float* ap = acc[mi * 4 + ni];
                *(__half2*)&Dh[row0 * 136 + col]       = __floats2half2_rn(ap[0], ap[1]);
                *(__half2*)&Dh[(row0 + 8) * 136 + col] = __floats2half2_rn(ap[2], ap[3]);
            }
        __syncthreads();

        int row = tid >> 1, half128 = tid & 1;
        const uint4* src = (const uint4*)(Dh + row * 136 + half128 * 64);
        uint4* dst = (uint4*)(g_t + ((size_t)b * MTOT + mbase + row) * 1024
                              + nbase + half128 * 64);
#pragma unroll
        for (int s = 0; s < 8; s++) dst[s] = src[s];
    }
}

// ---------------------------------------------------------------------------
// Combine: out[b,o,oy,ox] = leaky( d[b,o]*sum_{j,i} t[b,ji,o, ((oy+j-1)>>1)*32
//          + ((ox+i-1)>>1)] + bias[o] + noise[b,oy,ox] ), bounds-checked.
// grid (512 o, 8 b) x 256 threads; t row for (b,o) staged in smem (18KB).
__global__ void __launch_bounds__(256, 4) k_comb(const float* __restrict__ noise,
                                                 const float* __restrict__ bias,
                                                 float* __restrict__ out) {
    __shared__ __half ts[9 * 1024];
    int o = blockIdx.x;
    int b = blockIdx.y;
    int tid = threadIdx.x;

    // load 9 tap rows: uint4 = 8 halfs; 9*128 = 1152 vec loads
    {
        const uint4* gt4 = (const uint4*)g_t;
        uint4* st4 = (uint4*)ts;
        size_t rbase = ((size_t)b * MTOT + o) * 128;   // row in uint4 units
#pragma unroll
        for (int s = 0; s < 5; s++) {
            int idx = tid + 256 * s;
            if (idx < 1152) {
                int ji = (idx >> 7);
                int seg = idx & 127;
                st4[idx] = gt4[rbase + (size_t)ji * 512 * 128 + seg];
            }
        }
    }
    __syncthreads();

    float dv = g_d[b * 512 + o];
    float bv = bias[o];
    const float* nz = noise + b * 4096;
    float* op = out + (((size_t)b * 512 + o) << 12);

#pragma unroll 4
    for (int it = 0; it < 16; it++) {
        int pix = it * 256 + tid;
        int oy = pix >> 6, ox = pix & 63;
        float acc = 0.f;
#pragma unroll
        for (int j = 0; j < 3; j++) {
            int uy = oy + j - 1;
            if ((unsigned)uy >= 64u) continue;
            int iy = uy >> 1;
#pragma unroll
            for (int i = 0; i < 3; i++) {
                int ux = ox + i - 1;
                if ((unsigned)ux >= 64u) continue;
                acc += __half2float(ts[(j * 3 + i) * 1024 + iy * 32 + (ux >> 1)]);
            }
        }
        float v = acc * dv + bv + nz[pix];
        v = (v >= 0.f) ? v : 0.2f * v;
        op[pix] = v;
    }
}

// ---------------------------------------------------------------------------
extern "C" void kernel_launch(void* const* d_in, const int* in_sizes, int n_in,
                              void* d_out, int out_size) {
    const float* x      = (const float*)d_in[0];
    const float* style  = (const float*)d_in[1];
    const float* noise  = (const float*)d_in[2];
    const float* conv_w = (const float*)d_in[3];
    const float* fc_w   = (const float*)d_in[4];
    const float* fc_b   = (const float*)d_in[5];
    const float* bias   = (const float*)d_in[6];
    float* out = (float*)d_out;

    cudaFuncSetAttribute(k_gemm9, cudaFuncAttributeMaxDynamicSharedMemorySize, SMEM_REQ);

    k_style<<<8, 512>>>(style, fc_w, fc_b);
    k_w9<<<1024, 256>>>(conv_w);
    k_demod<<<dim3(2, 8), 256>>>();
    k_xsplit<<<4096, 256>>>(x);
    k_gemm9<<<dim3(8, 36, 8), 256, SMEM_REQ>>>();
    k_comb<<<dim3(512, 8), 256>>>(noise, bias, out);
}

// round 14
// speedup vs baseline: 1.3269x; 1.3269x over previous
#include <cuda_runtime.h>
#include <cuda_fp16.h>
#include <cstdint>

// Problem constants
#define BB 8
#define CC 512
#define OO 512
#define MTOT 4608          // 9 taps * 512 o
#define KK 512
#define KC 32              // K per chunk
#define NKC 16             // KK / KC
#define LDR 80             // smem row stride (bytes): 64B data + 16B pad
#define STG 20480          // per-stage: W 10240 + X 10240

// Scratch (no allocation allowed -> device globals)
__device__ float g_smod[BB * CC];                     // 1 + style @ fc_w^T + fc_b
__device__ float g_d[BB * OO];                        // demod scale
__device__ float g_w2t[CC * OO];                      // sum_k conv_w^2, [c][o]
__device__ __align__(16) __half g_w9[9 * OO * CC];    // [ji*512+o][c] fp16
__device__ __align__(16) __half g_xt[BB * 1024 * CC]; // fp16(x*smod) TRANSPOSED [b][pix][c]
__device__ __align__(16) __half g_t[(size_t)BB * MTOT * 1024]; // taps [b][ji*512+o][pix]

// ---------------------------------------------------------------------------
__device__ __forceinline__ uint32_t smem_u32(const void* p) {
    uint32_t a;
    asm("{ .reg .u64 t; cvta.to.shared.u64 t, %1; cvt.u32.u64 %0, t; }"
        : "=r"(a) : "l"(p));
    return a;
}
#define CP_ASYNC16(dst, src) \
    asm volatile("cp.async.cg.shared.global [%0], [%1], 16;\n" \
                 :: "r"(dst), "l"(__cvta_generic_to_global(src)))
#define CP_COMMIT()  asm volatile("cp.async.commit_group;\n" ::: "memory")
#define CP_WAIT1()   asm volatile("cp.async.wait_group 1;\n" ::: "memory")

#define LDMATRIX_X4(r, addr) \
    asm volatile("ldmatrix.sync.aligned.m8n8.x4.shared.b16 {%0,%1,%2,%3}, [%4];\n" \
                 : "=r"((r)[0]), "=r"((r)[1]), "=r"((r)[2]), "=r"((r)[3]) : "r"(addr))

#define MMA16816(d, a, b0v, b1v) \
    asm volatile("mma.sync.aligned.m16n8k16.row.col.f32.f16.f16.f32 " \
                 "{%0,%1,%2,%3},{%4,%5,%6,%7},{%8,%9},{%0,%1,%2,%3};\n" \
                 : "+f"((d)[0]), "+f"((d)[1]), "+f"((d)[2]), "+f"((d)[3]) \
                 : "r"((a)[0]), "r"((a)[1]), "r"((a)[2]), "r"((a)[3]), \
                   "r"(b0v), "r"(b1v))

// ---------------------------------------------------------------------------
// s[b][c] = 1 + fc_b[c] + sum_k style[b][k] * fc_w[c][k]
__global__ void k_style(const float* __restrict__ style,
                        const float* __restrict__ fc_w,
                        const float* __restrict__ fc_b) {
    __shared__ float ss[512];
    int b = blockIdx.x;
    int c = threadIdx.x;
    ss[c] = style[b * 512 + c];
    __syncthreads();
    const float4* wrow = (const float4*)(fc_w + (size_t)c * 512);
    float acc = 0.f;
#pragma unroll 4
    for (int k = 0; k < 128; k++) {
        float4 w4 = wrow[k];
        acc += w4.x * ss[4 * k + 0] + w4.y * ss[4 * k + 1]
             + w4.z * ss[4 * k + 2] + w4.w * ss[4 * k + 3];
    }
    g_smod[b * 512 + c] = acc + fc_b[c] + 1.0f;
}

// ---------------------------------------------------------------------------
// W9 prep: g_w9[(ji*512+o)*512+c] = fp16(conv_w[o][c][j][i]); also W2^T.
__global__ void k_w9(const float* __restrict__ conv_w) {
    int t = blockIdx.x * 256 + threadIdx.x;   // 262144 threads
    int c = t & 511;
    int o = t >> 9;
    const float* wp = conv_w + ((size_t)o * 512 + c) * 9;
    float s2 = 0.f;
#pragma unroll
    for (int q = 0; q < 9; q++) {
        float w = wp[q];
        s2 += w * w;
        g_w9[((size_t)q * 512 + o) * 512 + c] = __float2half_rn(w);
    }
    g_w2t[c * 512 + o] = s2;
}

// ---------------------------------------------------------------------------
// d[b][o] = rsqrt( sum_c smod[b][c]^2 * W2[o][c] + 1e-8 )
__global__ void k_demod() {
    __shared__ float s2[512];
    int b = blockIdx.y;
    int o = blockIdx.x * 256 + threadIdx.x;
    {
        float a = g_smod[b * 512 + threadIdx.x];
        float bv = g_smod[b * 512 + threadIdx.x + 256];
        s2[threadIdx.x] = a * a;
        s2[threadIdx.x + 256] = bv * bv;
    }
    __syncthreads();
    float acc = 1e-8f;
#pragma unroll 4
    for (int c = 0; c < 512; c++)
        acc += s2[c] * g_w2t[c * 512 + o];
    g_d[b * 512 + o] = rsqrtf(acc);
}

// ---------------------------------------------------------------------------
// Transposed modulated input: g_xt[b][pix][c] = fp16(x[b][c][pix]*smod[b][c]).
// 32c x 128pix tile per block; smem [32][129] float transpose, conflict-free.
// grid (8 pixtile, 16 ctile, 8 b) x 256
__global__ void k_xsplit_t(const float* __restrict__ x) {
    __shared__ float ts[32 * 129];
    int b = blockIdx.z;
    int c0 = blockIdx.y * 32;
    int p0 = blockIdx.x * 128;
    int tid = threadIdx.x;

    const float* xp = x + (((size_t)b * 512 + c0) << 10) + p0;
#pragma unroll
    for (int s = 0; s < 4; s++) {
        int idx = tid + 256 * s;           // 1024 float4 loads
        int c = idx >> 5, seg = idx & 31;
        float4 v = *(const float4*)(xp + ((size_t)c << 10) + seg * 4);
        float sm = g_smod[b * 512 + c0 + c];
        float* d = &ts[c * 129 + seg * 4];
        d[0] = v.x * sm; d[1] = v.y * sm; d[2] = v.z * sm; d[3] = v.w * sm;
    }
    __syncthreads();

    int pix = tid >> 1, h = tid & 1;       // 16 c-values per thread
    __half hv[16];
#pragma unroll
    for (int i = 0; i < 16; i++)
        hv[i] = __float2half_rn(ts[(h * 16 + i) * 129 + pix]);
    uint4* dst = (uint4*)(g_xt + (((size_t)b << 10) + p0 + pix) * 512 + c0 + h * 16);
    dst[0] = *(uint4*)&hv[0];
    dst[1] = *(uint4*)&hv[8];
}

// ---------------------------------------------------------------------------
// Dense tap GEMM: per b: T[m][pix] = sum_c W9[m][c] * xt[b][pix][c]
// m = ji*512+o (4608 rows). CTA tile 128m x 128pix, K=512 in 16 chunks of 32.
// BOTH operands row-major-K in smem (rows x 64B, LDR=80), pure cp.async,
// non-trans ldmatrix — byte-for-byte the R9 proven inner loop.
// smem stage s at s*20480 (W@0, X@10240); epilogue reuses as Dh[128][136] fp16.
#define SMEM_REQ (2 * STG)

__global__ void __launch_bounds__(256, 2) k_gemm9(void) {
    extern __shared__ __align__(16) char smem_raw[];
    char* abase = smem_raw;
    uint32_t base = smem_u32(smem_raw);

    const int tid = threadIdx.x;
    const int wid = tid >> 5;
    const int lane = tid & 31;

    const int nbase = blockIdx.x * 128;          // pixel base
    const int mbase = blockIdx.y * 128;          // (ji,o) row base
    const int b = blockIdx.z;

    const __half* gw = g_w9 + (size_t)mbase * 512;
    const __half* gx = g_xt + (((size_t)b << 10) + nbase) * 512;

    // loader constants (2 x 16B per thread per operand)
    const int lrow = tid >> 2;       // 0..63 (+64 second pass)
    const int lseg = tid & 3;

    // warp tile: 2x4 warp grid -> warp M=64, N=32 (R9 mapping)
    const int moff = (wid & 1) * 64;
    const int noff = (wid >> 1) * 32;
    const uint32_t aoff = (uint32_t)((moff + (lane & 15)) * LDR + ((lane >> 4) * 8) * 2);
    const uint32_t boff = (uint32_t)((noff + (lane & 7) + ((lane >> 4) << 3)) * LDR
                                     + (((lane >> 3) & 1) * 8) * 2);

    float acc[16][4];
#pragma unroll
    for (int q = 0; q < 16; q++)
#pragma unroll
        for (int r = 0; r < 4; r++) acc[q][r] = 0.f;

    // stage chunk kc into buffer bf (W 128x64B + X 128x64B)
    auto stage = [&](int kc, int bf) {
        uint32_t wdst = base + bf * STG;
#pragma unroll
        for (int s = 0; s < 2; s++) {
            int row = lrow + 64 * s;
            CP_ASYNC16(wdst + row * LDR + lseg * 16,
                       gw + (size_t)row * 512 + kc * 32 + lseg * 8);
        }
        uint32_t xdst = wdst + 10240;
#pragma unroll
        for (int s = 0; s < 2; s++) {
            int row = lrow + 64 * s;
            CP_ASYNC16(xdst + row * LDR + lseg * 16,
                       gx + (size_t)row * 512 + kc * 32 + lseg * 8);
        }
    };

    stage(0, 0); CP_COMMIT();
    stage(1, 1); CP_COMMIT();

    for (int kc = 0; kc < NKC; kc++) {
        int bf = kc & 1;
        CP_WAIT1();                 // group kc landed (kc+1 may fly)
        __syncthreads();

        uint32_t wS = base + bf * STG;
        uint32_t xS = wS + 10240;
#pragma unroll
        for (int ks = 0; ks < 2; ks++) {
            uint32_t a[4][4], bb[2][4];
#pragma unroll
            for (int mi = 0; mi < 4; mi++)
                LDMATRIX_X4(a[mi], wS + aoff + ks * 32 + mi * 16 * LDR);
#pragma unroll
            for (int nf = 0; nf < 2; nf++)
                LDMATRIX_X4(bb[nf], xS + boff + ks * 32 + nf * 16 * LDR);
#pragma unroll
            for (int mi = 0; mi < 4; mi++)
#pragma unroll
                for (int ni = 0; ni < 4; ni++)
                    MMA16816(acc[mi * 4 + ni], a[mi],
                             bb[ni >> 1][(ni & 1) * 2], bb[ni >> 1][(ni & 1) * 2 + 1]);
        }
        __syncthreads();            // all warps done reading buf bf
        if (kc + 2 < NKC) stage(kc + 2, bf);
        CP_COMMIT();                // uniform group count
    }

    // ---- epilogue: fp32 accums -> fp16 smem tile -> coalesced store ----
    {
        __half* Dh = (__half*)abase;          // [128][136]
        int g = lane >> 2, t4 = lane & 3;
#pragma unroll
        for (int mi = 0; mi < 4; mi++)
#pragma unroll
            for (int ni = 0; ni < 4; ni++) {
                int row0 = moff + mi * 16 + g;
                int col = noff + ni * 8 + t4 * 2;
                float* ap = acc[mi * 4 + ni];
                *(__half2*)&Dh[row0 * 136 + col]       = __floats2half2_rn(ap[0], ap[1]);
                *(__half2*)&Dh[(row0 + 8) * 136 + col] = __floats2half2_rn(ap[2], ap[3]);
            }
        __syncthreads();

        int row = tid >> 1, half128 = tid & 1;
        const uint4* src = (const uint4*)(Dh + row * 136 + half128 * 64);
        uint4* dst = (uint4*)(g_t + ((size_t)b * MTOT + mbase + row) * 1024
                              + nbase + half128 * 64);
#pragma unroll
        for (int s = 0; s < 8; s++) dst[s] = src[s];
    }
}

// ---------------------------------------------------------------------------
// Combine: out[b,o,oy,ox] = leaky( d[b,o]*sum_{j,i} t[b,ji,o][((oy+j-1)>>1)*32
//          + ((ox+i-1)>>1)] + bias[o] + noise[b,oy,ox] ), bounds-checked.
// grid (512 o, 8 b) x 256; t rows for (b,o) staged in smem (18KB).
__global__ void __launch_bounds__(256, 4) k_comb(const float* __restrict__ noise,
                                                 const float* __restrict__ bias,
                                                 float* __restrict__ out) {
    __shared__ __half ts[9 * 1024];
    int o = blockIdx.x;
    int b = blockIdx.y;
    int tid = threadIdx.x;

    {
        const uint4* gt4 = (const uint4*)g_t;
        uint4* st4 = (uint4*)ts;
        size_t rbase = ((size_t)b * MTOT + o) * 128;   // row in uint4 units
#pragma unroll
        for (int s = 0; s < 5; s++) {
            int idx = tid + 256 * s;
            if (idx < 1152) {
                int ji = (idx >> 7);
                int seg = idx & 127;
                st4[idx] = gt4[rbase + (size_t)ji * 512 * 128 + seg];
            }
        }
    }
    __syncthreads();

    float dv = g_d[b * 512 + o];
    float bv = bias[o];
    const float* nz = noise + b * 4096;
    float* op = out + (((size_t)b * 512 + o) << 12);

#pragma unroll 4
    for (int it = 0; it < 16; it++) {
        int pix = it * 256 + tid;
        int oy = pix >> 6, ox = pix & 63;
        float acc = 0.f;
#pragma unroll
        for (int j = 0; j < 3; j++) {
            int uy = oy + j - 1;
            if ((unsigned)uy >= 64u) continue;
            int iy = uy >> 1;
#pragma unroll
            for (int i = 0; i < 3; i++) {
                int ux = ox + i - 1;
                if ((unsigned)ux >= 64u) continue;
                acc += __half2float(ts[(j * 3 + i) * 1024 + iy * 32 + (ux >> 1)]);
            }
        }
        float v = acc * dv + bv + nz[pix];
        v = (v >= 0.f) ? v : 0.2f * v;
        op[pix] = v;
    }
}

// ---------------------------------------------------------------------------
extern "C" void kernel_launch(void* const* d_in, const int* in_sizes, int n_in,
                              void* d_out, int out_size) {
    const float* x      = (const float*)d_in[0];
    const float* style  = (const float*)d_in[1];
    const float* noise  = (const float*)d_in[2];
    const float* conv_w = (const float*)d_in[3];
    const float* fc_w   = (const float*)d_in[4];
    const float* fc_b   = (const float*)d_in[5];
    const float* bias   = (const float*)d_in[6];
    float* out = (float*)d_out;

    cudaFuncSetAttribute(k_gemm9, cudaFuncAttributeMaxDynamicSharedMemorySize, SMEM_REQ);

    k_style<<<8, 512>>>(style, fc_w, fc_b);
    k_w9<<<1024, 256>>>(conv_w);
    k_demod<<<dim3(2, 8), 256>>>();
    k_xsplit_t<<<dim3(8, 16, 8), 256>>>(x);
    k_gemm9<<<dim3(8, 36, 8), 256, SMEM_REQ>>>();
    k_comb<<<dim3(512, 8), 256>>>(noise, bias, out);
}

// round 15
// speedup vs baseline: 1.4191x; 1.0695x over previous
#include <cuda_runtime.h>
#include <cuda_fp16.h>
#include <cstdint>

// Problem constants
#define BB 8
#define CC 512
#define OO 512
#define MTOT 4608          // 9 taps * 512 o
#define KK 512
#define KC 64              // K per chunk
#define NKC 8              // KK / KC
#define LDR 144            // smem row stride (bytes): 128B data + 16B pad
#define STG 36864          // per-stage: W 18432 + X 18432

// Scratch (no allocation allowed -> device globals)
__device__ float g_smod[BB * CC];                     // 1 + style @ fc_w^T + fc_b
__device__ float g_d[BB * OO];                        // demod scale
__device__ float g_w2t[CC * OO];                      // sum_k conv_w^2, [c][o]
__device__ __align__(16) __half g_w9[9 * OO * CC];    // [ji*512+o][c] fp16
__device__ __align__(16) __half g_xt[BB * 1024 * CC]; // fp16(x*smod) TRANSPOSED [b][pix][c]
__device__ __align__(16) __half g_t[(size_t)BB * MTOT * 1024]; // taps [b][ji*512+o][pix]

// ---------------------------------------------------------------------------
__device__ __forceinline__ uint32_t smem_u32(const void* p) {
    uint32_t a;
    asm("{ .reg .u64 t; cvta.to.shared.u64 t, %1; cvt.u32.u64 %0, t; }"
        : "=r"(a) : "l"(p));
    return a;
}
#define CP_ASYNC16(dst, src) \
    asm volatile("cp.async.cg.shared.global [%0], [%1], 16;\n" \
                 :: "r"(dst), "l"(__cvta_generic_to_global(src)))
#define CP_COMMIT()  asm volatile("cp.async.commit_group;\n" ::: "memory")
#define CP_WAIT1()   asm volatile("cp.async.wait_group 1;\n" ::: "memory")

#define LDMATRIX_X4(r, addr) \
    asm volatile("ldmatrix.sync.aligned.m8n8.x4.shared.b16 {%0,%1,%2,%3}, [%4];\n" \
                 : "=r"((r)[0]), "=r"((r)[1]), "=r"((r)[2]), "=r"((r)[3]) : "r"(addr))

#define MMA16816(d, a, b0v, b1v) \
    asm volatile("mma.sync.aligned.m16n8k16.row.col.f32.f16.f16.f32 " \
                 "{%0,%1,%2,%3},{%4,%5,%6,%7},{%8,%9},{%0,%1,%2,%3};\n" \
                 : "+f"((d)[0]), "+f"((d)[1]), "+f"((d)[2]), "+f"((d)[3]) \
                 : "r"((a)[0]), "r"((a)[1]), "r"((a)[2]), "r"((a)[3]), \
                   "r"(b0v), "r"(b1v))

// ---------------------------------------------------------------------------
// s[b][c] = 1 + fc_b[c] + sum_k style[b][k] * fc_w[c][k]
__global__ void k_style(const float* __restrict__ style,
                        const float* __restrict__ fc_w,
                        const float* __restrict__ fc_b) {
    __shared__ float ss[512];
    int b = blockIdx.x;
    int c = threadIdx.x;
    ss[c] = style[b * 512 + c];
    __syncthreads();
    const float4* wrow = (const float4*)(fc_w + (size_t)c * 512);
    float acc = 0.f;
#pragma unroll 4
    for (int k = 0; k < 128; k++) {
        float4 w4 = wrow[k];
        acc += w4.x * ss[4 * k + 0] + w4.y * ss[4 * k + 1]
             + w4.z * ss[4 * k + 2] + w4.w * ss[4 * k + 3];
    }
    g_smod[b * 512 + c] = acc + fc_b[c] + 1.0f;
}

// ---------------------------------------------------------------------------
// W9 prep: g_w9[(ji*512+o)*512+c] = fp16(conv_w[o][c][j][i]); also W2^T.
__global__ void k_w9(const float* __restrict__ conv_w) {
    int t = blockIdx.x * 256 + threadIdx.x;   // 262144 threads
    int c = t & 511;
    int o = t >> 9;
    const float* wp = conv_w + ((size_t)o * 512 + c) * 9;
    float s2 = 0.f;
#pragma unroll
    for (int q = 0; q < 9; q++) {
        float w = wp[q];
        s2 += w * w;
        g_w9[((size_t)q * 512 + o) * 512 + c] = __float2half_rn(w);
    }
    g_w2t[c * 512 + o] = s2;
}

// ---------------------------------------------------------------------------
// d[b][o] = rsqrt( sum_c smod[b][c]^2 * W2[o][c] + 1e-8 )
__global__ void k_demod() {
    __shared__ float s2[512];
    int b = blockIdx.y;
    int o = blockIdx.x * 256 + threadIdx.x;
    {
        float a = g_smod[b * 512 + threadIdx.x];
        float bv = g_smod[b * 512 + threadIdx.x + 256];
        s2[threadIdx.x] = a * a;
        s2[threadIdx.x + 256] = bv * bv;
    }
    __syncthreads();
    float acc = 1e-8f;
#pragma unroll 4
    for (int c = 0; c < 512; c++)
        acc += s2[c] * g_w2t[c * 512 + o];
    g_d[b * 512 + o] = rsqrtf(acc);
}

// ---------------------------------------------------------------------------
// Transposed modulated input: g_xt[b][pix][c] = fp16(x[b][c][pix]*smod[b][c]).
// 32c x 128pix tile per block; smem [32][129] float transpose, conflict-free.
__global__ void k_xsplit_t(const float* __restrict__ x) {
    __shared__ float ts[32 * 129];
    int b = blockIdx.z;
    int c0 = blockIdx.y * 32;
    int p0 = blockIdx.x * 128;
    int tid = threadIdx.x;

    const float* xp = x + (((size_t)b * 512 + c0) << 10) + p0;
#pragma unroll
    for (int s = 0; s < 4; s++) {
        int idx = tid + 256 * s;           // 1024 float4 loads
        int c = idx >> 5, seg = idx & 31;
        float4 v = *(const float4*)(xp + ((size_t)c << 10) + seg * 4);
        float sm = g_smod[b * 512 + c0 + c];
        float* d = &ts[c * 129 + seg * 4];
        d[0] = v.x * sm; d[1] = v.y * sm; d[2] = v.z * sm; d[3] = v.w * sm;
    }
    __syncthreads();

    int pix = tid >> 1, h = tid & 1;       // 16 c-values per thread
    __half hv[16];
#pragma unroll
    for (int i = 0; i < 16; i++)
        hv[i] = __float2half_rn(ts[(h * 16 + i) * 129 + pix]);
    uint4* dst = (uint4*)(g_xt + (((size_t)b << 10) + p0 + pix) * 512 + c0 + h * 16);
    dst[0] = *(uint4*)&hv[0];
    dst[1] = *(uint4*)&hv[8];
}

// ---------------------------------------------------------------------------
// Dense tap GEMM: per b: T[m][pix] = sum_c W9[m][c] * xt[b][pix][c]
// m = ji*512+o (4608 rows). CTA tile 128m x 128pix, K=512 in 8 chunks of 64.
// BOTH operands row-major-K (rows x 128B, LDR=144), pure cp.async,
// non-trans ldmatrix. 64 HMMA per warp between barriers (2x R14 density).
// smem stage s at s*36864 (W@0, X@18432); epilogue reuses as Dh[128][136] fp16.
#define SMEM_REQ (2 * STG)

__global__ void __launch_bounds__(256, 2) k_gemm9(void) {
    extern __shared__ __align__(16) char smem_raw[];
    char* abase = smem_raw;
    uint32_t base = smem_u32(smem_raw);

    const int tid = threadIdx.x;
    const int wid = tid >> 5;
    const int lane = tid & 31;

    const int nbase = blockIdx.x * 128;          // pixel base
    const int mbase = blockIdx.y * 128;          // (ji,o) row base
    const int b = blockIdx.z;

    const __half* gw = g_w9 + (size_t)mbase * 512;
    const __half* gx = g_xt + (((size_t)b << 10) + nbase) * 512;

    // loader constants: 1024 x 16B per operand -> 4 passes x (row=opid>>3, seg=opid&7)
    const int lrow = tid >> 3;       // 0..31 (+32 per pass)
    const int lseg = tid & 7;

    // warp tile: 2x4 warp grid -> warp M=64, N=32
    const int moff = (wid & 1) * 64;
    const int noff = (wid >> 1) * 32;
    const uint32_t aoff = (uint32_t)((moff + (lane & 15)) * LDR + ((lane >> 4) * 8) * 2);
    const uint32_t boff = (uint32_t)((noff + (lane & 7) + ((lane >> 4) << 3)) * LDR
                                     + (((lane >> 3) & 1) * 8) * 2);

    float acc[16][4];
#pragma unroll
    for (int q = 0; q < 16; q++)
#pragma unroll
        for (int r = 0; r < 4; r++) acc[q][r] = 0.f;

    // stage chunk kc into buffer bf (W 128x128B + X 128x128B)
    auto stage = [&](int kc, int bf) {
        uint32_t wdst = base + bf * STG;
#pragma unroll
        for (int s = 0; s < 4; s++) {
            int row = lrow + 32 * s;
            CP_ASYNC16(wdst + row * LDR + lseg * 16,
                       gw + (size_t)row * 512 + kc * 64 + lseg * 8);
        }
        uint32_t xdst = wdst + 18432;
#pragma unroll
        for (int s = 0; s < 4; s++) {
            int row = lrow + 32 * s;
            CP_ASYNC16(xdst + row * LDR + lseg * 16,
                       gx + (size_t)row * 512 + kc * 64 + lseg * 8);
        }
    };

    stage(0, 0); CP_COMMIT();
    stage(1, 1); CP_COMMIT();

    for (int kc = 0; kc < NKC; kc++) {
        int bf = kc & 1;
        CP_WAIT1();                 // group kc landed (kc+1 may fly)
        __syncthreads();

        uint32_t wS = base + bf * STG;
        uint32_t xS = wS + 18432;
#pragma unroll
        for (int ks = 0; ks < 4; ks++) {
            uint32_t a[4][4], bb[2][4];
#pragma unroll
            for (int mi = 0; mi < 4; mi++)
                LDMATRIX_X4(a[mi], wS + aoff + ks * 32 + mi * 16 * LDR);
#pragma unroll
            for (int nf = 0; nf < 2; nf++)
                LDMATRIX_X4(bb[nf], xS + boff + ks * 32 + nf * 16 * LDR);
#pragma unroll
            for (int mi = 0; mi < 4; mi++)
#pragma unroll
                for (int ni = 0; ni < 4; ni++)
                    MMA16816(acc[mi * 4 + ni], a[mi],
                             bb[ni >> 1][(ni & 1) * 2], bb[ni >> 1][(ni & 1) * 2 + 1]);
        }
        __syncthreads();            // all warps done reading buf bf
        if (kc + 2 < NKC) stage(kc + 2, bf);
        CP_COMMIT();                // uniform group count
    }

    // ---- epilogue: fp32 accums -> fp16 smem tile -> coalesced store ----
    {
        __half* Dh = (__half*)abase;          // [128][136]
        int g = lane >> 2, t4 = lane & 3;
#pragma unroll
        for (int mi = 0; mi < 4; mi++)
#pragma unroll
            for (int ni = 0; ni < 4; ni++) {
                int row0 = moff + mi * 16 + g;
                int col = noff + ni * 8 + t4 * 2;
                float* ap = acc[mi * 4 + ni];
                *(__half2*)&Dh[row0 * 136 + col]       = __floats2half2_rn(ap[0], ap[1]);
                *(__half2*)&Dh[(row0 + 8) * 136 + col] = __floats2half2_rn(ap[2], ap[3]);
            }
        __syncthreads();

        int row = tid >> 1, half128 = tid & 1;
        const uint4* src = (const uint4*)(Dh + row * 136 + half128 * 64);
        uint4* dst = (uint4*)(g_t + ((size_t)b * MTOT + mbase + row) * 1024
                              + nbase + half128 * 64);
#pragma unroll
        for (int s = 0; s < 8; s++) dst[s] = src[s];
    }
}

// ---------------------------------------------------------------------------
// Combine: out[b,o,oy,ox] = leaky( d[b,o]*sum_{j,i} t[b,ji,o][((oy+j-1)>>1)*32
//          + ((ox+i-1)>>1)] + bias[o] + noise[b,oy,ox] ), bounds-checked.
// grid (512 o, 8 b) x 256; t rows for (b,o) staged in smem (18KB).
__global__ void __launch_bounds__(256, 4) k_comb(const float* __restrict__ noise,
                                                 const float* __restrict__ bias,
                                                 float* __restrict__ out) {
    __shared__ __half ts[9 * 1024];
    int o = blockIdx.x;
    int b = blockIdx.y;
    int tid = threadIdx.x;

    {
        const uint4* gt4 = (const uint4*)g_t;
        uint4* st4 = (uint4*)ts;
        size_t rbase = ((size_t)b * MTOT + o) * 128;   // row in uint4 units
#pragma unroll
        for (int s = 0; s < 5; s++) {
            int idx = tid + 256 * s;
            if (idx < 1152) {
                int ji = (idx >> 7);
                int seg = idx & 127;
                st4[idx] = gt4[rbase + (size_t)ji * 512 * 128 + seg];
            }
        }
    }
    __syncthreads();

    float dv = g_d[b * 512 + o];
    float bv = bias[o];
    const float* nz = noise + b * 4096;
    float* op = out + (((size_t)b * 512 + o) << 12);

#pragma unroll 4
    for (int it = 0; it < 16; it++) {
        int pix = it * 256 + tid;
        int oy = pix >> 6, ox = pix & 63;
        float acc = 0.f;
#pragma unroll
        for (int j = 0; j < 3; j++) {
            int uy = oy + j - 1;
            if ((unsigned)uy >= 64u) continue;
            int iy = uy >> 1;
#pragma unroll
            for (int i = 0; i < 3; i++) {
                int ux = ox + i - 1;
                if ((unsigned)ux >= 64u) continue;
                acc += __half2float(ts[(j * 3 + i) * 1024 + iy * 32 + (ux >> 1)]);
            }
        }
        float v = acc * dv + bv + nz[pix];
        v = (v >= 0.f) ? v : 0.2f * v;
        op[pix] = v;
    }
}

// ---------------------------------------------------------------------------
extern "C" void kernel_launch(void* const* d_in, const int* in_sizes, int n_in,
                              void* d_out, int out_size) {
    const float* x      = (const float*)d_in[0];
    const float* style  = (const float*)d_in[1];
    const float* noise  = (const float*)d_in[2];
    const float* conv_w = (const float*)d_in[3];
    const float* fc_w   = (const float*)d_in[4];
    const float* fc_b   = (const float*)d_in[5];
    const float* bias   = (const float*)d_in[6];
    float* out = (float*)d_out;

    cudaFuncSetAttribute(k_gemm9, cudaFuncAttributeMaxDynamicSharedMemorySize, SMEM_REQ);

    k_style<<<8, 512>>>(style, fc_w, fc_b);
    k_w9<<<1024, 256>>>(conv_w);
    k_demod<<<dim3(2, 8), 256>>>();
    k_xsplit_t<<<dim3(8, 16, 8), 256>>>(x);
    k_gemm9<<<dim3(8, 36, 8), 256, SMEM_REQ>>>();
    k_comb<<<dim3(512, 8), 256>>>(noise, bias, out);
}

// round 17
// speedup vs baseline: 1.4301x; 1.0078x over previous
#include <cuda_runtime.h>
#include <cuda_fp16.h>
#include <cstdint>

// Problem constants
#define BB 8
#define CC 512
#define OO 512
#define MTOT 4608          // 9 taps * 512 o
#define KK 512
#define KC 64              // K per chunk
#define NKC 8              // KK / KC
#define LDR 144            // smem row stride (bytes): 128B data + 16B pad
#define STG 36864          // per-stage: W 18432 + X 18432
#define NSTG 3             // smem ring stages

// Scratch (no allocation allowed -> device globals)
__device__ float g_smod[BB * CC];                     // 1 + style @ fc_w^T + fc_b
__device__ float g_d[BB * OO];                        // demod scale
__device__ float g_w2t[CC * OO];                      // sum_k conv_w^2, [c][o]
__device__ __align__(16) __half g_w9[9 * OO * CC];    // [ji*512+o][c] fp16
__device__ __align__(16) __half g_xt[BB * 1024 * CC]; // fp16(x*smod) TRANSPOSED [b][pix][c]
__device__ __align__(16) __half g_t[(size_t)BB * MTOT * 1024]; // taps [b][ji*512+o][pix]

// ---------------------------------------------------------------------------
__device__ __forceinline__ uint32_t smem_u32(const void* p) {
    uint32_t a;
    asm("{ .reg .u64 t; cvta.to.shared.u64 t, %1; cvt.u32.u64 %0, t; }"
        : "=r"(a) : "l"(p));
    return a;
}
#define CP_ASYNC16(dst, src) \
    asm volatile("cp.async.cg.shared.global [%0], [%1], 16;\n" \
                 :: "r"(dst), "l"(__cvta_generic_to_global(src)))
#define CP_COMMIT()  asm volatile("cp.async.commit_group;\n" ::: "memory")
#define CP_WAIT1()   asm volatile("cp.async.wait_group 1;\n" ::: "memory")

#define LDMATRIX_X4(r, addr) \
    asm volatile("ldmatrix.sync.aligned.m8n8.x4.shared.b16 {%0,%1,%2,%3}, [%4];\n" \
                 : "=r"((r)[0]), "=r"((r)[1]), "=r"((r)[2]), "=r"((r)[3]) : "r"(addr))

#define MMA16816(d, a, b0v, b1v) \
    asm volatile("mma.sync.aligned.m16n8k16.row.col.f32.f16.f16.f32 " \
                 "{%0,%1,%2,%3},{%4,%5,%6,%7},{%8,%9},{%0,%1,%2,%3};\n" \
                 : "+f"((d)[0]), "+f"((d)[1]), "+f"((d)[2]), "+f"((d)[3]) \
                 : "r"((a)[0]), "r"((a)[1]), "r"((a)[2]), "r"((a)[3]), \
                   "r"(b0v), "r"(b1v))

// ---------------------------------------------------------------------------
// s[b][c] = 1 + fc_b[c] + sum_k style[b][k] * fc_w[c][k]
__global__ void k_style(const float* __restrict__ style,
                        const float* __restrict__ fc_w,
                        const float* __restrict__ fc_b) {
    __shared__ float ss[512];
    int b = blockIdx.x;
    int c = threadIdx.x;
    ss[c] = style[b * 512 + c];
    __syncthreads();
    const float4* wrow = (const float4*)(fc_w + (size_t)c * 512);
    float acc = 0.f;
#pragma unroll 4
    for (int k = 0; k < 128; k++) {
        float4 w4 = wrow[k];
        acc += w4.x * ss[4 * k + 0] + w4.y * ss[4 * k + 1]
             + w4.z * ss[4 * k + 2] + w4.w * ss[4 * k + 3];
    }
    g_smod[b * 512 + c] = acc + fc_b[c] + 1.0f;
}

// ---------------------------------------------------------------------------
// W9 prep: g_w9[(ji*512+o)*512+c] = fp16(conv_w[o][c][j][i]); also W2^T.
__global__ void k_w9(const float* __restrict__ conv_w) {
    int t = blockIdx.x * 256 + threadIdx.x;   // 262144 threads
    int c = t & 511;
    int o = t >> 9;
    const float* wp = conv_w + ((size_t)o * 512 + c) * 9;
    float s2 = 0.f;
#pragma unroll
    for (int q = 0; q < 9; q++) {
        float w = wp[q];
        s2 += w * w;
        g_w9[((size_t)q * 512 + o) * 512 + c] = __float2half_rn(w);
    }
    g_w2t[c * 512 + o] = s2;
}

// ---------------------------------------------------------------------------
// d[b][o] = rsqrt( sum_c smod[b][c]^2 * W2[o][c] + 1e-8 )
__global__ void k_demod() {
    __shared__ float s2[512];
    int b = blockIdx.y;
    int o = blockIdx.x * 256 + threadIdx.x;
    {
        float a = g_smod[b * 512 + threadIdx.x];
        float bv = g_smod[b * 512 + threadIdx.x + 256];
        s2[threadIdx.x] = a * a;
        s2[threadIdx.x + 256] = bv * bv;
    }
    __syncthreads();
    float acc = 1e-8f;
#pragma unroll 4
    for (int c = 0; c < 512; c++)
        acc += s2[c] * g_w2t[c * 512 + o];
    g_d[b * 512 + o] = rsqrtf(acc);
}

// ---------------------------------------------------------------------------
// Transposed modulated input: g_xt[b][pix][c] = fp16(x[b][c][pix]*smod[b][c]).
// 32c x 128pix tile per block; smem [32][129] float transpose, conflict-free.
__global__ void k_xsplit_t(const float* __restrict__ x) {
    __shared__ float ts[32 * 129];
    int b = blockIdx.z;
    int c0 = blockIdx.y * 32;
    int p0 = blockIdx.x * 128;
    int tid = threadIdx.x;

    const float* xp = x + (((size_t)b * 512 + c0) << 10) + p0;
#pragma unroll
    for (int s = 0; s < 4; s++) {
        int idx = tid + 256 * s;           // 1024 float4 loads
        int c = idx >> 5, seg = idx & 31;
        float4 v = *(const float4*)(xp + ((size_t)c << 10) + seg * 4);
        float sm = g_smod[b * 512 + c0 + c];
        float* d = &ts[c * 129 + seg * 4];
        d[0] = v.x * sm; d[1] = v.y * sm; d[2] = v.z * sm; d[3] = v.w * sm;
    }
    __syncthreads();

    int pix = tid >> 1, h = tid & 1;       // 16 c-values per thread
    __half hv[16];
#pragma unroll
    for (int i = 0; i < 16; i++)
        hv[i] = __float2half_rn(ts[(h * 16 + i) * 129 + pix]);
    uint4* dst = (uint4*)(g_xt + (((size_t)b << 10) + p0 + pix) * 512 + c0 + h * 16);
    dst[0] = *(uint4*)&hv[0];
    dst[1] = *(uint4*)&hv[8];
}

// ---------------------------------------------------------------------------
// Dense tap GEMM: per b: T[m][pix] = sum_c W9[m][c] * xt[b][pix][c]
// m = ji*512+o (4608 rows). CTA tile 128m x 128pix, K=512 in 8 chunks of 64.
// THREE-stage smem ring, prefetch distance 2, ONE __syncthreads per chunk:
//   wait_group 1 -> sync -> stage(kc+2) -> commit -> 64 HMMAs.
// Restage target buffer (kc+2)%3 == (kc-1)%3 was fully read before this
// iteration's barrier, so no second barrier is needed.
// smem stage s at s*36864 (W@0, X@18432); epilogue reuses as Dh[128][136] fp16.
#define SMEM_REQ (NSTG * STG)

__global__ void __launch_bounds__(256, 2) k_gemm9(void) {
    extern __shared__ __align__(16) char smem_raw[];
    char* abase = smem_raw;
    uint32_t base = smem_u32(smem_raw);

    const int tid = threadIdx.x;
    const int wid = tid >> 5;
    const int lane = tid & 31;

    const int nbase = blockIdx.x * 128;          // pixel base
    const int mbase = blockIdx.y * 128;          // (ji,o) row base
    const int b = blockIdx.z;

    const __half* gw = g_w9 + (size_t)mbase * 512;
    const __half* gx = g_xt + (((size_t)b << 10) + nbase) * 512;

    // loader constants: 1024 x 16B per operand -> 4 passes x (row=opid>>3, seg=opid&7)
    const int lrow = tid >> 3;       // 0..31 (+32 per pass)
    const int lseg = tid & 7;

    // warp tile: 2x4 warp grid -> warp M=64, N=32
    const int moff = (wid & 1) * 64;
    const int noff = (wid >> 1) * 32;
    const uint32_t aoff = (uint32_t)((moff + (lane & 15)) * LDR + ((lane >> 4) * 8) * 2);
    const uint32_t boff = (uint32_t)((noff + (lane & 7) + ((lane >> 4) << 3)) * LDR
                                     + (((lane >> 3) & 1) * 8) * 2);

    float acc[16][4];
#pragma unroll
    for (int q = 0; q < 16; q++)
#pragma unroll
        for (int r = 0; r < 4; r++) acc[q][r] = 0.f;

    // stage chunk kc into ring buffer bf (W 128x128B + X 128x128B)
    auto stage = [&](int kc, int bf) {
        uint32_t wdst = base + bf * STG;
#pragma unroll
        for (int s = 0; s < 4; s++) {
            int row = lrow + 32 * s;
            CP_ASYNC16(wdst + row * LDR + lseg * 16,
                       gw + (size_t)row * 512 + kc * 64 + lseg * 8);
        }
        uint32_t xdst = wdst + 18432;
#pragma unroll
        for (int s = 0; s < 4; s++) {
            int row = lrow + 32 * s;
            CP_ASYNC16(xdst + row * LDR + lseg * 16,
                       gx + (size_t)row * 512 + kc * 64 + lseg * 8);
        }
    };

    stage(0, 0); CP_COMMIT();
    stage(1, 1); CP_COMMIT();

    int cur = 0;
    for (int kc = 0; kc < NKC; kc++) {
        CP_WAIT1();                 // group kc landed (kc+1 may still fly)
        __syncthreads();            // visibility + all warps done reading buf (kc-1)

        // restage into buffer (kc+2)%3 == (kc-1)%3 — safe post-barrier
        int nx = cur + 2; if (nx >= NSTG) nx -= NSTG;
        if (kc + 2 < NKC) stage(kc + 2, nx);
        CP_COMMIT();                // uniform group count

        uint32_t wS = base + cur * STG;
        uint32_t xS = wS + 18432;
#pragma unroll
        for (int ks = 0; ks < 4; ks++) {
            uint32_t a[4][4], bb[2][4];
#pragma unroll
            for (int mi = 0; mi < 4; mi++)
                LDMATRIX_X4(a[mi], wS + aoff + ks * 32 + mi * 16 * LDR);
#pragma unroll
            for (int nf = 0; nf < 2; nf++)
                LDMATRIX_X4(bb[nf], xS + boff + ks * 32 + nf * 16 * LDR);
#pragma unroll
            for (int mi = 0; mi < 4; mi++)
#pragma unroll
                for (int ni = 0; ni < 4; ni++)
                    MMA16816(acc[mi * 4 + ni], a[mi],
                             bb[ni >> 1][(ni & 1) * 2], bb[ni >> 1][(ni & 1) * 2 + 1]);
        }

        cur = cur + 1; if (cur == NSTG) cur = 0;
    }
    __syncthreads();                // all MMAs done before smem reuse

    // ---- epilogue: fp32 accums -> fp16 smem tile -> coalesced store ----
    {
        __half* Dh = (__half*)abase;          // [128][136]
        int g = lane >> 2, t4 = lane & 3;
#pragma unroll
        for (int mi = 0; mi < 4; mi++)
#pragma unroll
            for (int ni = 0; ni < 4; ni++) {
                int row0 = moff + mi * 16 + g;
                int col = noff + ni * 8 + t4 * 2;
                float* ap = acc[mi * 4 + ni];
                *(__half2*)&Dh[row0 * 136 + col]       = __floats2half2_rn(ap[0], ap[1]);
                *(__half2*)&Dh[(row0 + 8) * 136 + col] = __floats2half2_rn(ap[2], ap[3]);
            }
        __syncthreads();

        int row = tid >> 1, half128 = tid & 1;
        const uint4* src = (const uint4*)(Dh + row * 136 + half128 * 64);
        uint4* dst = (uint4*)(g_t + ((size_t)b * MTOT + mbase + row) * 1024
                              + nbase + half128 * 64);
#pragma unroll
        for (int s = 0; s < 8; s++) dst[s] = src[s];
    }
}

// ---------------------------------------------------------------------------
// Combine: out[b,o,oy,ox] = leaky( d[b,o]*sum_{j,i} t[b,ji,o][((oy+j-1)>>1)*32
//          + ((ox+i-1)>>1)] + bias[o] + noise[b,oy,ox] ), bounds-checked.
// grid (512 o, 8 b) x 256; t rows for (b,o) staged in smem (18KB).
__global__ void __launch_bounds__(256, 4) k_comb(const float* __restrict__ noise,
                                                 const float* __restrict__ bias,
                                                 float* __restrict__ out) {
    __shared__ __half ts[9 * 1024];
    int o = blockIdx.x;
    int b = blockIdx.y;
    int tid = threadIdx.x;

    {
        const uint4* gt4 = (const uint4*)g_t;
        uint4* st4 = (uint4*)ts;
        size_t rbase = ((size_t)b * MTOT + o) * 128;   // row in uint4 units
#pragma unroll
        for (int s = 0; s < 5; s++) {
            int idx = tid + 256 * s;
            if (idx < 1152) {
                int ji = (idx >> 7);
                int seg = idx & 127;
                st4[idx] = gt4[rbase + (size_t)ji * 512 * 128 + seg];
            }
        }
    }
    __syncthreads();

    float dv = g_d[b * 512 + o];
    float bv = bias[o];
    const float* nz = noise + b * 4096;
    float* op = out + (((size_t)b * 512 + o) << 12);

#pragma unroll 4
    for (int it = 0; it < 16; it++) {
        int pix = it * 256 + tid;
        int oy = pix >> 6, ox = pix & 63;
        float acc = 0.f;
#pragma unroll
        for (int j = 0; j < 3; j++) {
            int uy = oy + j - 1;
            if ((unsigned)uy >= 64u) continue;
            int iy = uy >> 1;
#pragma unroll
            for (int i = 0; i < 3; i++) {
                int ux = ox + i - 1;
                if ((unsigned)ux >= 64u) continue;
                acc += __half2float(ts[(j * 3 + i) * 1024 + iy * 32 + (ux >> 1)]);
            }
        }
        float v = acc * dv + bv + nz[pix];
        v = (v >= 0.f) ? v : 0.2f * v;
        op[pix] = v;
    }
}

// ---------------------------------------------------------------------------
extern "C" void kernel_launch(void* const* d_in, const int* in_sizes, int n_in,
                              void* d_out, int out_size) {
    const float* x      = (const float*)d_in[0];
    const float* style  = (const float*)d_in[1];
    const float* noise  = (const float*)d_in[2];
    const float* conv_w = (const float*)d_in[3];
    const float* fc_w   = (const float*)d_in[4];
    const float* fc_b   = (const float*)d_in[5];
    const float* bias   = (const float*)d_in[6];
    float* out = (float*)d_out;

    cudaFuncSetAttribute(k_gemm9, cudaFuncAttributeMaxDynamicSharedMemorySize, SMEM_REQ);

    k_style<<<8, 512>>>(style, fc_w, fc_b);
    k_w9<<<1024, 256>>>(conv_w);
    k_demod<<<dim3(2, 8), 256>>>();
    k_xsplit_t<<<dim3(8, 16, 8), 256>>>(x);
    k_gemm9<<<dim3(8, 36, 8), 256, SMEM_REQ>>>();
    k_comb<<<dim3(512, 8), 256>>>(noise, bias, out);
}